// round 12
// baseline (speedup 1.0000x reference)
#include <cuda_runtime.h>
#include <math.h>

#define MAXN 50000
#define MAXE 800000
#define BN_EPS 1e-5f

// ---------------- scratch (no allocations allowed) ----------------
__device__ float g_bufA[(size_t)MAXN * 256];
__device__ float g_bufB[(size_t)MAXN * 256];
__device__ float g_dinv[MAXN];
__device__ int   g_cnt[MAXN];
__device__ int   g_rowptr[MAXN + 1];
__device__ int   g_cursor[MAXN];
__device__ int   g_blkoff[512];
__device__ int2  g_csr[MAXE];       // {src_node, __float_as_int(edge_weight)}
__device__ float g_sum[3][128];     // per-GCN-layer BN column sums
__device__ float g_sumsq[3][128];
__device__ int   g_is64;            // edge_index dtype flag (probed on device)

// ---------------- packed f32x2 helpers (sm_100+ PTX) ----------------
__device__ __forceinline__ unsigned long long pack2(float lo, float hi) {
    unsigned long long r;
    asm("mov.b64 %0, {%1, %2};" : "=l"(r) : "f"(lo), "f"(hi));
    return r;
}
__device__ __forceinline__ void unpack2(unsigned long long v, float& lo, float& hi) {
    asm("mov.b64 {%0, %1}, %2;" : "=f"(lo), "=f"(hi) : "l"(v));
}
__device__ __forceinline__ void ffma2(unsigned long long& d,
                                      unsigned long long a, unsigned long long b) {
    asm("fma.rn.f32x2 %0, %1, %2, %0;" : "+l"(d) : "l"(a), "l"(b));
}

// ---------------- init: zero counters/stats + edge dtype probe ------------
// Probe: int64 edges with values in [0,N) have every odd 32-bit word zero;
// int32 edges have random nonzero odd words w.h.p. Sample 128 words.
__global__ void init_kernel(const unsigned* __restrict__ w, int n) {
    int i = blockIdx.x * blockDim.x + threadIdx.x;
    if (i < n) g_cnt[i] = 0;
    if (i < 128) {
#pragma unroll
        for (int l = 0; l < 3; l++) { g_sum[l][i] = 0.0f; g_sumsq[l][i] = 0.0f; }
    }
    if (blockIdx.x == 0 && threadIdx.x < 32) {
        int t = threadIdx.x;
        unsigned v = w[2 * t + 1] | w[2 * (t + 32) + 1] |
                     w[2 * (t + 64) + 1] | w[2 * (t + 96) + 1];
        unsigned any = __ballot_sync(0xffffffffu, v != 0);
        if (t == 0) g_is64 = (any == 0) ? 1 : 0;
    }
}

__device__ __forceinline__ void load_edge(const void* ei, int E, int e,
                                          int& s, int& d) {
    if (g_is64) {
        const long long* p = (const long long*)ei;
        s = (int)p[e];
        d = (int)p[e + E];
    } else {
        const int* p = (const int*)ei;
        s = p[e];
        d = p[e + E];
    }
}

__global__ void count_kernel(const void* __restrict__ ei, int E) {
    int e = blockIdx.x * blockDim.x + threadIdx.x;
    if (e < E) {
        int s, d;
        load_edge(ei, E, e, s, d);
        atomicAdd(&g_cnt[d], 1);
    }
}

// ---- multi-block scan, phase 1: per-block sums of g_cnt (+ dinv) --------
__global__ void partial_kernel(int n) {
    __shared__ int ws[8];
    int t = threadIdx.x;
    int i = blockIdx.x * 256 + t;
    int c = (i < n) ? g_cnt[i] : 0;
    if (i < n) g_dinv[i] = rsqrtf((float)c + 1.0f);
    int v = c;
#pragma unroll
    for (int o = 1; o < 32; o <<= 1) v += __shfl_xor_sync(0xffffffffu, v, o);
    if ((t & 31) == 0) ws[t >> 5] = v;
    __syncthreads();
    if (t == 0) {
        int s = 0;
#pragma unroll
        for (int k = 0; k < 8; k++) s += ws[k];
        g_blkoff[blockIdx.x] = s;   // raw block sum (scanned in phase 2)
    }
}

// ---- phase 2: exclusive scan of <=512 block sums (one warp) -------------
__global__ void blkscan_kernel(int nb) {
    int lane = threadIdx.x;                 // 32 threads
    int run = 0;
    for (int base = 0; base < nb; base += 32) {
        int idx = base + lane;
        int c = (idx < nb) ? g_blkoff[idx] : 0;
        int v = c;
#pragma unroll
        for (int o = 1; o < 32; o <<= 1) {
            int u = __shfl_up_sync(0xffffffffu, v, o);
            if (lane >= o) v += u;
        }
        if (idx < nb) g_blkoff[idx] = run + v - c;   // exclusive
        run += __shfl_sync(0xffffffffu, v, 31);      // chunk total
    }
}

// ---- phase 3: in-block exclusive scan + block offset -> rowptr/cursor ---
__global__ void rowptr_kernel(int n, int E) {
    __shared__ int ws[8];
    __shared__ int wo[8];
    int t = threadIdx.x;
    int lane = t & 31, w = t >> 5;
    int i = blockIdx.x * 256 + t;
    int c = (i < n) ? g_cnt[i] : 0;
    int v = c;
#pragma unroll
    for (int o = 1; o < 32; o <<= 1) {
        int u = __shfl_up_sync(0xffffffffu, v, o);
        if (lane >= o) v += u;
    }
    if (lane == 31) ws[w] = v;
    __syncthreads();
    if (t == 0) {
        int r = 0;
#pragma unroll
        for (int k = 0; k < 8; k++) { wo[k] = r; r += ws[k]; }
    }
    __syncthreads();
    int excl = v - c + wo[w] + g_blkoff[blockIdx.x];
    if (i < n) {
        g_rowptr[i] = excl;
        g_cursor[i] = excl;
    }
    if (blockIdx.x == 0 && t == 0) g_rowptr[n] = E;
}

__global__ void fill_kernel(const void* __restrict__ ei, int E) {
    int e = blockIdx.x * blockDim.x + threadIdx.x;
    if (e < E) {
        int s, d;
        load_edge(ei, E, e, s, d);
        int p = atomicAdd(&g_cursor[d], 1);
        g_csr[p] = make_int2(s, __float_as_int(g_dinv[s] * g_dinv[d]));
    }
}

// ---------------- dense matmul: FFMA2-packed, persistent row-tile loop ----
// 512 threads; each warp computes TM=4 rows of a 64-row tile; blocks loop
// over row tiles so the W tile (smem) is loaded ONCE per block.
// APPLY_BN: computes BN scale/shift from raw column sums in-block, then fuses
// y = relu(x*scale+shift) into the X load (BN+ReLU of the previous layer).
template<int FIN, int FOUT, bool RELU, bool BIAS, bool APPLY_BN>
__global__ void __launch_bounds__(512)
matmul_kernel(const float* __restrict__ X, const float* __restrict__ W,
              const float* __restrict__ bias,
              const float* __restrict__ bsum, const float* __restrict__ bsq,
              const float* __restrict__ bng, const float* __restrict__ bnbe,
              float* __restrict__ Y, int n, int numTiles) {
    extern __shared__ float sm[];
    float* sW  = sm;
    float* sSc = sm + FIN * FOUT;
    float* sSh = sSc + FIN;
    const int tid = threadIdx.x;
    for (int i = tid; i < FIN * FOUT; i += 512) sW[i] = W[i];
    if (APPLY_BN && tid < FIN) {
        float inv_n = 1.0f / (float)n;
        float m   = bsum[tid] * inv_n;
        float var = bsq[tid] * inv_n - m * m;
        float sc  = bng[tid] * rsqrtf(var + BN_EPS);
        sSc[tid] = sc;
        sSh[tid] = bnbe[tid] - m * sc;
    }
    __syncthreads();                          // sW/sSc/sSh read-only below

    constexpr int TM  = 4;
    constexpr int XR  = FIN / 32;             // FIN multiple of 32
    constexpr int TNP = (FOUT + 63) / 64;     // column pairs per lane

    const int warp = tid >> 5;
    const int lane = tid & 31;
    const unsigned long long* sW64 = (const unsigned long long*)sW;

    for (int tb = blockIdx.x; tb < numTiles; tb += gridDim.x) {
        const int row0 = (tb * 16 + warp) * TM;
        if (row0 >= n) continue;

        float xr[TM][XR];
#pragma unroll
        for (int t = 0; t < TM; t++) {
            int r = row0 + t;
#pragma unroll
            for (int j = 0; j < XR; j++) {
                int f = lane + 32 * j;
                float v = (r < n) ? X[(size_t)r * FIN + f] : 0.0f;
                if (APPLY_BN) v = fmaxf(v * sSc[f] + sSh[f], 0.0f);
                xr[t][j] = v;
            }
        }

        unsigned long long acc[TM][TNP];
#pragma unroll
        for (int t = 0; t < TM; t++)
#pragma unroll
            for (int p = 0; p < TNP; p++) acc[t][p] = 0ULL;

#pragma unroll
        for (int jk = 0; jk < XR; jk++) {
#pragma unroll
            for (int l = 0; l < 32; l++) {
                const int k = jk * 32 + l;
                unsigned long long wp[TNP];
#pragma unroll
                for (int p = 0; p < TNP; p++) {
                    int pc = lane + 32 * p;                // pair index
                    wp[p] = (FOUT % 64 == 0 || 2 * pc < FOUT)
                            ? sW64[k * (FOUT / 2) + pc] : 0ULL;
                }
#pragma unroll
                for (int t = 0; t < TM; t++) {
                    float xv = __shfl_sync(0xffffffffu, xr[t][jk], l);
                    unsigned long long xp = pack2(xv, xv);
#pragma unroll
                    for (int p = 0; p < TNP; p++) ffma2(acc[t][p], xp, wp[p]);
                }
            }
        }

#pragma unroll
        for (int t = 0; t < TM; t++) {
            int r = row0 + t;
            if (r < n) {
#pragma unroll
                for (int p = 0; p < TNP; p++) {
                    int pc = lane + 32 * p;
                    int c  = 2 * pc;
                    if (FOUT % 64 == 0 || c < FOUT) {
                        float lo, hi;
                        unpack2(acc[t][p], lo, hi);
                        if (BIAS) { lo += bias[c]; hi += bias[c + 1]; }
                        if (RELU) { lo = fmaxf(lo, 0.0f); hi = fmaxf(hi, 0.0f); }
                        ((float2*)(Y + (size_t)r * FOUT))[pc] = make_float2(lo, hi);
                    }
                }
            }
        }
    }
}

// ---------------- neighbor gather (CSR int2, float4) + fused self-loop
//                  + bias + fused BN column stats (block smem reduction) ---
// Edge records are prefetched one iteration ahead; the independent epilogue
// loads (dinv, self-loop features, bias) are hoisted above the loop so they
// overlap the gather chain instead of serializing at the tail.
template<int F>
__global__ void gather4_kernel(const float* __restrict__ H,
                               const float* __restrict__ bias,
                               float* __restrict__ Y,
                               float* __restrict__ outSum,
                               float* __restrict__ outSq, int n) {
    constexpr int FQ = F / 4;
    __shared__ float sS[F];
    __shared__ float sQ[F];
    const int tid = blockIdx.x * blockDim.x + threadIdx.x;
    const int node = tid / FQ;
    const int f4 = tid % FQ;
    const bool active = (node < n);

    if (threadIdx.x < F) { sS[threadIdx.x] = 0.0f; sQ[threadIdx.x] = 0.0f; }
    __syncthreads();

    if (active) {
        const float4* __restrict__ H4 = (const float4*)H;
        int beg = g_rowptr[node];
        int end = g_rowptr[node + 1];
        // issue independent loads early so they fly under the gather chain
        float  dv = g_dinv[node];
        float4 hs = H4[(size_t)node * FQ + f4];       // self-loop features
        float4 b4 = ((const float4*)bias)[f4];
        float ax = 0.f, ay = 0.f, az = 0.f, aw = 0.f;
        int2 e = (beg < end) ? g_csr[beg] : make_int2(0, 0);
        for (int j = beg; j < end; j++) {
            int2 cur = e;
            if (j + 1 < end) e = g_csr[j + 1];        // prefetch next record
            float w = __int_as_float(cur.y);
            float4 hv = __ldg(&H4[(size_t)cur.x * FQ + f4]);
            ax += hv.x * w; ay += hv.y * w; az += hv.z * w; aw += hv.w * w;
        }
        float sl = dv * dv;
        float4 o;
        o.x = ax + hs.x * sl + b4.x;
        o.y = ay + hs.y * sl + b4.y;
        o.z = az + hs.z * sl + b4.z;
        o.w = aw + hs.w * sl + b4.w;
        ((float4*)Y)[(size_t)node * FQ + f4] = o;
        // block-local BN stat accumulation
        atomicAdd(&sS[4 * f4 + 0], o.x); atomicAdd(&sQ[4 * f4 + 0], o.x * o.x);
        atomicAdd(&sS[4 * f4 + 1], o.y); atomicAdd(&sQ[4 * f4 + 1], o.y * o.y);
        atomicAdd(&sS[4 * f4 + 2], o.z); atomicAdd(&sQ[4 * f4 + 2], o.z * o.z);
        atomicAdd(&sS[4 * f4 + 3], o.w); atomicAdd(&sQ[4 * f4 + 3], o.w * o.w);
    }
    __syncthreads();
    if (threadIdx.x < F) {
        atomicAdd(&outSum[threadIdx.x], sS[threadIdx.x]);
        atomicAdd(&outSq[threadIdx.x],  sQ[threadIdx.x]);
    }
}

// ---------------- launcher ----------------
extern "C" void kernel_launch(void* const* d_in, const int* in_sizes, int n_in,
                              void* d_out, int out_size) {
    const float* x  = (const float*)d_in[0];
    const void*  ei = d_in[1];                 // int64 OR int32 (probed on device)
    const float *W1 = (const float*)d_in[2],  *b1  = (const float*)d_in[3];
    const float *W2 = (const float*)d_in[4],  *b2  = (const float*)d_in[5];
    const float *W3 = (const float*)d_in[6],  *b3  = (const float*)d_in[7];
    const float *g1 = (const float*)d_in[8],  *be1 = (const float*)d_in[9];
    const float *g2 = (const float*)d_in[10], *be2 = (const float*)d_in[11];
    const float *g3 = (const float*)d_in[12], *be3 = (const float*)d_in[13];
    const float *Wf1 = (const float*)d_in[14], *bf1 = (const float*)d_in[15];
    const float *Wf2 = (const float*)d_in[16], *bf2 = (const float*)d_in[17];
    const float *Wf3 = (const float*)d_in[18], *bf3 = (const float*)d_in[19];
    const float *Wf4 = (const float*)d_in[20], *bf4 = (const float*)d_in[21];
    float* out = (float*)d_out;

    const int n = in_sizes[0] / 128;
    const int E = in_sizes[1] / 2;

    // smem sizes: W tile + BN scale/shift
    const int sm1  = (128 * 32  + 2 * 128) * 4;
    const int sm2  = (32  * 64  + 2 * 32 ) * 4;
    const int sm3  = (64  * 128 + 2 * 64 ) * 4;
    const int smf1 = (128 * 256 + 2 * 128) * 4;
    const int smf2 = (256 * 128 + 2 * 256) * 4;
    const int smf3 = (128 * 64  + 2 * 128) * 4;
    const int smf4 = (64  * 10  + 2 * 64 ) * 4;

    cudaFuncSetAttribute(matmul_kernel<128, 256, true, true, true>,
                         cudaFuncAttributeMaxDynamicSharedMemorySize, smf1);
    cudaFuncSetAttribute(matmul_kernel<256, 128, true, true, false>,
                         cudaFuncAttributeMaxDynamicSharedMemorySize, smf2);

    float *pA = nullptr, *pB = nullptr, *pSum = nullptr, *pSq = nullptr;
    cudaGetSymbolAddress((void**)&pA, g_bufA);
    cudaGetSymbolAddress((void**)&pB, g_bufB);
    cudaGetSymbolAddress((void**)&pSum, g_sum);
    cudaGetSymbolAddress((void**)&pSq,  g_sumsq);
    float *s1 = pSum,       *q1 = pSq;
    float *s2 = pSum + 128, *q2 = pSq + 128;
    float *s3 = pSum + 256, *q3 = pSq + 256;

    const int mt = (n + 63) / 64;              // 64-row tiles
    const int gSmall = (mt < 592) ? mt : 592;  // up to 4 blocks/SM (small smem)
    const int gBig   = (mt < 148) ? mt : 148;  // 1 block/SM (130KB smem)
    const int nb = (n + 255) / 256;            // scan blocks

    // ---- CSR build (once; reused by all 3 GCN layers) ----
    init_kernel<<<(n + 255) / 256, 256>>>((const unsigned*)ei, n);
    count_kernel<<<(E + 255) / 256, 256>>>(ei, E);
    partial_kernel<<<nb, 256>>>(n);
    blkscan_kernel<<<1, 32>>>(nb);
    rowptr_kernel<<<nb, 256>>>(n, E);
    fill_kernel<<<(E + 255) / 256, 256>>>(ei, E);

    // ---- GCN layer 1: 128 -> 32 ----
    matmul_kernel<128, 32, false, false, false><<<gSmall, 512, sm1>>>(
        x, W1, nullptr, nullptr, nullptr, nullptr, nullptr, pA, n, mt);
    gather4_kernel<32><<<(n * 8 + 255) / 256, 256>>>(pA, b1, pB, s1, q1, n);

    // ---- GCN layer 2: 32 -> 64 (BN1+ReLU fused into X load) ----
    matmul_kernel<32, 64, false, false, true><<<gSmall, 512, sm2>>>(
        pB, W2, nullptr, s1, q1, g1, be1, pA, n, mt);
    gather4_kernel<64><<<(n * 16 + 255) / 256, 256>>>(pA, b2, pB, s2, q2, n);

    // ---- GCN layer 3: 64 -> 128 (BN2+ReLU fused) ----
    matmul_kernel<64, 128, false, false, true><<<gSmall, 512, sm3>>>(
        pB, W3, nullptr, s2, q2, g2, be2, pA, n, mt);
    gather4_kernel<128><<<(n * 32 + 255) / 256, 256>>>(pA, b3, pB, s3, q3, n);

    // ---- MLP head (BN3+ReLU fused into first layer) ----
    matmul_kernel<128, 256, true,  true, true ><<<gBig, 512, smf1>>>(
        pB, Wf1, bf1, s3, q3, g3, be3, pA, n, mt);
    matmul_kernel<256, 128, true,  true, false><<<gBig, 512, smf2>>>(
        pA, Wf2, bf2, nullptr, nullptr, nullptr, nullptr, pB, n, mt);
    matmul_kernel<128, 64,  true,  true, false><<<gSmall, 512, smf3>>>(
        pB, Wf3, bf3, nullptr, nullptr, nullptr, nullptr, pA, n, mt);
    matmul_kernel<64,  10,  false, true, false><<<gSmall, 512, smf4>>>(
        pA, Wf4, bf4, nullptr, nullptr, nullptr, nullptr, out, n, mt);
}